// round 1
// baseline (speedup 1.0000x reference)
#include <cuda_runtime.h>
#include <math.h>

// ---------------- problem constants ----------------
#define BN    48
#define HHW   49            // H == W == 49
#define CCH   128           // channels
#define NHEAD 4
#define HD    32
#define NWIN  49            // windows per image (7x7)
#define NTOK  49            // tokens per window (7x7)
#define MROWS (BN*NWIN*NTOK)  // 115248 (== BN * 2401)
#define HID   512
#define QSCALE 0.17677669529663687f  // 32^-0.5

// ---------------- scratch (device globals, no allocation) ----------------
__device__ float g_xw [(size_t)MROWS*CCH];   // LN'd windowed input -> attn out -> LN2 out
__device__ float g_big[(size_t)MROWS*HID];   // qkv (stride 384) then mlp hidden (stride 512)
__device__ float g_x2 [(size_t)MROWS*CCH];   // residual after attention branch

// ---------------- LN1 + shift + window gather ----------------
__global__ void ln1_gather_kernel(const float* __restrict__ x,
                                  const float* __restrict__ w,
                                  const float* __restrict__ b) {
    int t = blockIdx.x;          // window token row 0..115247
    int c = threadIdx.x;         // channel 0..127
    int bw = t / NTOK, n = t - bw * NTOK;
    int bb = bw / NWIN, wi = bw - bb * NWIN;
    int R  = (wi / 7) * 7 + n / 7;
    int Cl = (wi % 7) * 7 + n % 7;
    int sr = R + 3;  if (sr >= 49) sr -= 49;   // cyclic shift (-3,-3)
    int sc = Cl + 3; if (sc >= 49) sc -= 49;
    const float* src = x + ((size_t)bb * 2401 + sr * 49 + sc) * CCH;
    float v = src[c];
    float s = v, s2 = v * v;
    #pragma unroll
    for (int o = 16; o > 0; o >>= 1) {
        s  += __shfl_xor_sync(0xffffffffu, s,  o);
        s2 += __shfl_xor_sync(0xffffffffu, s2, o);
    }
    __shared__ float red[8];
    int wid = c >> 5, lane = c & 31;
    if (lane == 0) { red[wid] = s; red[4 + wid] = s2; }
    __syncthreads();
    float ts  = red[0] + red[1] + red[2] + red[3];
    float ts2 = red[4] + red[5] + red[6] + red[7];
    float mean = ts * (1.f / 128.f);
    float var  = ts2 * (1.f / 128.f) - mean * mean;
    float rstd = rsqrtf(var + 1e-5f);
    g_xw[(size_t)t * CCH + c] = (v - mean) * rstd * w[c] + b[c];
}

// ---------------- LN2 (no gather) ----------------
__global__ void ln2_kernel(const float* __restrict__ w,
                           const float* __restrict__ b) {
    int t = blockIdx.x;
    int c = threadIdx.x;
    float v = g_x2[(size_t)t * CCH + c];
    float s = v, s2 = v * v;
    #pragma unroll
    for (int o = 16; o > 0; o >>= 1) {
        s  += __shfl_xor_sync(0xffffffffu, s,  o);
        s2 += __shfl_xor_sync(0xffffffffu, s2, o);
    }
    __shared__ float red[8];
    int wid = c >> 5, lane = c & 31;
    if (lane == 0) { red[wid] = s; red[4 + wid] = s2; }
    __syncthreads();
    float ts  = red[0] + red[1] + red[2] + red[3];
    float ts2 = red[4] + red[5] + red[6] + red[7];
    float mean = ts * (1.f / 128.f);
    float var  = ts2 * (1.f / 128.f) - mean * mean;
    float rstd = rsqrtf(var + 1e-5f);
    g_xw[(size_t)t * CCH + c] = (v - mean) * rstd * w[c] + b[c];
}

// ---------------- attention: one block per (window, head) ----------------
__device__ __forceinline__ int regn(int wq, int iq) {
    // region of row/col index wq*7+iq in 49: [0,42)=0, [42,46)=1, [46,49)=2
    return (wq < 6) ? 0 : ((iq < 4) ? 1 : 2);
}

__global__ void attn_kernel(const float* __restrict__ rpb) {
    int bw = blockIdx.x;        // 0..2351
    int h  = blockIdx.y;        // 0..3
    int w  = bw % NWIN;
    int tid = threadIdx.x;      // 128 threads

    __shared__ float q [49 * 33];
    __shared__ float k [49 * 33];
    __shared__ float vv[49 * 33];
    __shared__ float sc[49 * 50];

    const float* base = g_big + (size_t)bw * NTOK * 384;
    for (int idx = tid; idx < 49 * 32; idx += 128) {
        int n = idx >> 5, d = idx & 31;
        q [n * 33 + d] = base[n * 384 +       h * 32 + d];
        k [n * 33 + d] = base[n * 384 + 128 + h * 32 + d];
        vv[n * 33 + d] = base[n * 384 + 256 + h * 32 + d];
    }
    __syncthreads();

    // scores + relative position bias + shift mask
    int wh = w / 7, ww = w % 7;
    for (int e = tid; e < 49 * 49; e += 128) {
        int n = e / 49, m = e - n * 49;
        float a = 0.f;
        #pragma unroll
        for (int d = 0; d < 32; d++) a += q[n * 33 + d] * k[m * 33 + d];
        int i1 = n / 7, j1 = n % 7, i2 = m / 7, j2 = m % 7;
        int ridx = (i1 - i2 + 6) * 13 + (j1 - j2 + 6);
        a += rpb[ridx * 4 + h];
        // mask[w,n,m] = (mw[w,m] != mw[n,m]) ? -100 : 0   (faithful to ref broadcast)
        int mwW = regn(wh, i2) * 3 + regn(ww, j2);
        int mwN = regn(n / 7, i2) * 3 + regn(n % 7, j2);
        if (mwW != mwN) a -= 100.f;
        sc[n * 50 + m] = a;
    }
    __syncthreads();

    // softmax per row (one warp handles a row at a time)
    int wid = tid >> 5, lane = tid & 31;
    for (int n = wid; n < 49; n += 4) {
        float v1 = sc[n * 50 + lane];
        bool has2 = (lane + 32) < 49;
        float v2 = has2 ? sc[n * 50 + lane + 32] : -INFINITY;
        float mx = fmaxf(v1, v2);
        #pragma unroll
        for (int o = 16; o > 0; o >>= 1) mx = fmaxf(mx, __shfl_xor_sync(0xffffffffu, mx, o));
        float e1 = __expf(v1 - mx);
        float e2 = has2 ? __expf(v2 - mx) : 0.f;
        float s = e1 + e2;
        #pragma unroll
        for (int o = 16; o > 0; o >>= 1) s += __shfl_xor_sync(0xffffffffu, s, o);
        float inv = 1.f / s;
        sc[n * 50 + lane] = e1 * inv;
        if (has2) sc[n * 50 + lane + 32] = e2 * inv;
    }
    __syncthreads();

    // out = attn @ v  -> write [row, h*32+d] into g_xw (reused as attn-out buffer)
    for (int e = tid; e < 49 * 32; e += 128) {
        int n = e >> 5, d = e & 31;
        float a = 0.f;
        #pragma unroll
        for (int m = 0; m < 49; m++) a += sc[n * 50 + m] * vv[m * 33 + d];
        g_xw[((size_t)bw * NTOK + n) * CCH + h * 32 + d] = a;
    }
}

// ---------------- generic tiled SGEMM:  C = A[M,K] @ W[N,K]^T + bias, fused epilogue ----
// EPI 0: qkv   (A=g_xw,  out g_big stride 384, q columns scaled)
// EPI 1: proj  (A=g_xw,  out g_x2 via window-reverse scatter, + residual from aux=x)
// EPI 2: fc1   (A=g_xw,  out g_big stride 512, exact GELU)
// EPI 3: fc2   (A=g_big, out extC=d_out, + residual from g_x2)
template <int EPI>
__global__ void sgemm_kernel(const float* __restrict__ W,
                             const float* __restrict__ bias,
                             const float* __restrict__ aux,
                             float* __restrict__ extC,
                             int M, int N, int K) {
    __shared__ float As[8][128];
    __shared__ float Ws[8][128];
    const float* A = (EPI == 3) ? g_big : g_xw;

    int tid  = threadIdx.x;             // 256 threads
    int row0 = blockIdx.x * 128;
    int col0 = blockIdx.y * 128;
    int tx = tid & 15, ty = tid >> 4;   // 16x16 thread grid, 8x8 each

    float acc[8][8];
    #pragma unroll
    for (int i = 0; i < 8; i++)
        #pragma unroll
        for (int j = 0; j < 8; j++) acc[i][j] = 0.f;

    int lm = tid >> 1;          // 0..127
    int lk = (tid & 1) * 4;     // 0 or 4
    const float* Aptr = A + (size_t)(row0 + lm) * K + lk;
    const float* Wptr = W + (size_t)(col0 + lm) * K + lk;
    bool arow_ok = (row0 + lm) < M;

    for (int k0 = 0; k0 < K; k0 += 8) {
        float4 av = arow_ok ? *(const float4*)(Aptr + k0) : make_float4(0.f, 0.f, 0.f, 0.f);
        float4 wv = *(const float4*)(Wptr + k0);
        __syncthreads();
        As[lk + 0][lm] = av.x; As[lk + 1][lm] = av.y;
        As[lk + 2][lm] = av.z; As[lk + 3][lm] = av.w;
        Ws[lk + 0][lm] = wv.x; Ws[lk + 1][lm] = wv.y;
        Ws[lk + 2][lm] = wv.z; Ws[lk + 3][lm] = wv.w;
        __syncthreads();
        #pragma unroll
        for (int kk = 0; kk < 8; kk++) {
            float a[8], b[8];
            *(float4*)&a[0] = *(const float4*)&As[kk][ty * 8];
            *(float4*)&a[4] = *(const float4*)&As[kk][ty * 8 + 4];
            *(float4*)&b[0] = *(const float4*)&Ws[kk][tx * 8];
            *(float4*)&b[4] = *(const float4*)&Ws[kk][tx * 8 + 4];
            #pragma unroll
            for (int i = 0; i < 8; i++)
                #pragma unroll
                for (int j = 0; j < 8; j++) acc[i][j] += a[i] * b[j];
        }
    }

    #pragma unroll
    for (int i = 0; i < 8; i++) {
        int r = row0 + ty * 8 + i;
        if (r >= M) continue;
        size_t dest = 0;
        if (EPI == 1) {
            int bw = r / 49, tok = r - bw * 49;
            int bb = bw / 49, wi = bw - bb * 49;
            int R  = (wi / 7) * 7 + tok / 7;
            int Cl = (wi % 7) * 7 + tok % 7;
            int rr = R + 3;  if (rr >= 49) rr -= 49;   // reverse shift (+3,+3)
            int cc = Cl + 3; if (cc >= 49) cc -= 49;
            dest = ((size_t)bb * 2401 + rr * 49 + cc) * 128;
        }
        #pragma unroll
        for (int j = 0; j < 8; j++) {
            int n = col0 + tx * 8 + j;
            float v = acc[i][j] + bias[n];
            if (EPI == 0) {
                if (n < 128) v *= QSCALE;                 // q scaled after bias (matches ref)
                g_big[(size_t)r * 384 + n] = v;
            } else if (EPI == 1) {
                g_x2[dest + n] = aux[dest + n] + v;       // residual with shortcut x
            } else if (EPI == 2) {
                v = 0.5f * v * (1.f + erff(v * 0.70710678118654752f));  // exact GELU
                g_big[(size_t)r * 512 + n] = v;
            } else {
                extC[(size_t)r * 128 + n] = g_x2[(size_t)r * 128 + n] + v;
            }
        }
    }
}

// ---------------- launch ----------------
extern "C" void kernel_launch(void* const* d_in, const int* in_sizes, int n_in,
                              void* d_out, int out_size) {
    const float* x      = (const float*)d_in[0];
    const float* n1w    = (const float*)d_in[1];
    const float* n1b    = (const float*)d_in[2];
    const float* qkv_w  = (const float*)d_in[3];
    const float* qkv_b  = (const float*)d_in[4];
    const float* proj_w = (const float*)d_in[5];
    const float* proj_b = (const float*)d_in[6];
    const float* rpb    = (const float*)d_in[7];
    const float* n2w    = (const float*)d_in[8];
    const float* n2b    = (const float*)d_in[9];
    const float* fc1_w  = (const float*)d_in[10];
    const float* fc1_b  = (const float*)d_in[11];
    const float* fc2_w  = (const float*)d_in[12];
    const float* fc2_b  = (const float*)d_in[13];
    float* out = (float*)d_out;

    const int M = MROWS;                 // 115248
    const int gm = (M + 127) / 128;      // 901

    // 1) LN1 + shift + window partition
    ln1_gather_kernel<<<M, 128>>>(x, n1w, n1b);

    // 2) QKV GEMM (q pre-scaled)
    sgemm_kernel<0><<<dim3(gm, 3), 256>>>(qkv_w, qkv_b, nullptr, nullptr, M, 384, 128);

    // 3) windowed attention (bias + shift mask + softmax + @v)
    attn_kernel<<<dim3(BN * NWIN, NHEAD), 128>>>(rpb);

    // 4) proj GEMM + window reverse + reverse shift + residual -> x2
    sgemm_kernel<1><<<dim3(gm, 1), 256>>>(proj_w, proj_b, x, nullptr, M, 128, 128);

    // 5) LN2
    ln2_kernel<<<M, 128>>>(n2w, n2b);

    // 6) fc1 + exact GELU
    sgemm_kernel<2><<<dim3(gm, 4), 256>>>(fc1_w, fc1_b, nullptr, nullptr, M, 512, 128);

    // 7) fc2 + residual -> out
    sgemm_kernel<3><<<dim3(gm, 1), 256>>>(fc2_w, fc2_b, nullptr, out, M, 128, 512);
}

// round 2
// speedup vs baseline: 1.6425x; 1.6425x over previous
#include <cuda_runtime.h>
#include <math.h>
#include <stdint.h>

// ---------------- problem constants ----------------
#define BN    48
#define CCH   128
#define NHEAD 4
#define NWIN  49
#define NTOK  49
#define MROWS (BN*NWIN*NTOK)   // 115248
#define HID   512
#define QSCALE 0.17677669529663687f

// ---------------- scratch ----------------
__device__ float g_xw [(size_t)MROWS*CCH];
__device__ float g_big[(size_t)MROWS*HID];
__device__ float g_x2 [(size_t)MROWS*CCH];

// ---------------- helpers ----------------
__device__ __forceinline__ unsigned f2tf(float x) {
    unsigned u; asm("cvt.rna.tf32.f32 %0, %1;" : "=r"(u) : "f"(x)); return u;
}
__device__ __forceinline__ void mma_tf32(float c[4], unsigned a0, unsigned a1,
                                         unsigned a2, unsigned a3,
                                         unsigned b0, unsigned b1) {
    asm volatile("mma.sync.aligned.m16n8k8.row.col.f32.tf32.tf32.f32 "
                 "{%0,%1,%2,%3}, {%4,%5,%6,%7}, {%8,%9}, {%0,%1,%2,%3};"
                 : "+f"(c[0]), "+f"(c[1]), "+f"(c[2]), "+f"(c[3])
                 : "r"(a0), "r"(a1), "r"(a2), "r"(a3), "r"(b0), "r"(b1));
}

// ---------------- LN1 + shift + window gather ----------------
__global__ void ln1_gather_kernel(const float* __restrict__ x,
                                  const float* __restrict__ w,
                                  const float* __restrict__ b) {
    int t = blockIdx.x, c = threadIdx.x;
    int bw = t / NTOK, n = t - bw * NTOK;
    int bb = bw / NWIN, wi = bw - bb * NWIN;
    int R  = (wi / 7) * 7 + n / 7;
    int Cl = (wi % 7) * 7 + n % 7;
    int sr = R + 3;  if (sr >= 49) sr -= 49;
    int sc = Cl + 3; if (sc >= 49) sc -= 49;
    float v = x[((size_t)bb * 2401 + sr * 49 + sc) * CCH + c];
    float s = v, s2 = v * v;
    #pragma unroll
    for (int o = 16; o > 0; o >>= 1) {
        s  += __shfl_xor_sync(0xffffffffu, s,  o);
        s2 += __shfl_xor_sync(0xffffffffu, s2, o);
    }
    __shared__ float red[8];
    int wid = c >> 5, lane = c & 31;
    if (lane == 0) { red[wid] = s; red[4 + wid] = s2; }
    __syncthreads();
    float ts  = red[0] + red[1] + red[2] + red[3];
    float ts2 = red[4] + red[5] + red[6] + red[7];
    float mean = ts * (1.f / 128.f);
    float var  = ts2 * (1.f / 128.f) - mean * mean;
    float rstd = rsqrtf(var + 1e-5f);
    g_xw[(size_t)t * CCH + c] = (v - mean) * rstd * w[c] + b[c];
}

__global__ void ln2_kernel(const float* __restrict__ w,
                           const float* __restrict__ b) {
    int t = blockIdx.x, c = threadIdx.x;
    float v = g_x2[(size_t)t * CCH + c];
    float s = v, s2 = v * v;
    #pragma unroll
    for (int o = 16; o > 0; o >>= 1) {
        s  += __shfl_xor_sync(0xffffffffu, s,  o);
        s2 += __shfl_xor_sync(0xffffffffu, s2, o);
    }
    __shared__ float red[8];
    int wid = c >> 5, lane = c & 31;
    if (lane == 0) { red[wid] = s; red[4 + wid] = s2; }
    __syncthreads();
    float ts  = red[0] + red[1] + red[2] + red[3];
    float ts2 = red[4] + red[5] + red[6] + red[7];
    float mean = ts * (1.f / 128.f);
    float var  = ts2 * (1.f / 128.f) - mean * mean;
    float rstd = rsqrtf(var + 1e-5f);
    g_xw[(size_t)t * CCH + c] = (v - mean) * rstd * w[c] + b[c];
}

// ---------------- attention: one block per (window, head) ----------------
__device__ __forceinline__ int regn(int wq, int iq) {
    return (wq < 6) ? 0 : ((iq < 4) ? 1 : 2);
}

__global__ void attn_kernel(const float* __restrict__ rpb) {
    int bw = blockIdx.x, h = blockIdx.y;
    int w  = bw % NWIN;
    int tid = threadIdx.x;

    __shared__ float q [49 * 33];
    __shared__ float k [49 * 33];
    __shared__ float vv[49 * 33];
    __shared__ float sc[49 * 50];

    const float* base = g_big + (size_t)bw * NTOK * 384;
    for (int idx = tid; idx < 49 * 32; idx += 128) {
        int n = idx >> 5, d = idx & 31;
        q [n * 33 + d] = base[n * 384 +       h * 32 + d];
        k [n * 33 + d] = base[n * 384 + 128 + h * 32 + d];
        vv[n * 33 + d] = base[n * 384 + 256 + h * 32 + d];
    }
    __syncthreads();

    int wh = w / 7, ww = w % 7;
    for (int e = tid; e < 49 * 49; e += 128) {
        int n = e / 49, m = e - n * 49;
        float a = 0.f;
        #pragma unroll
        for (int d = 0; d < 32; d++) a += q[n * 33 + d] * k[m * 33 + d];
        int i1 = n / 7, j1 = n % 7, i2 = m / 7, j2 = m % 7;
        int ridx = (i1 - i2 + 6) * 13 + (j1 - j2 + 6);
        a += rpb[ridx * 4 + h];
        int mwW = regn(wh, i2) * 3 + regn(ww, j2);
        int mwN = regn(i1, i2) * 3 + regn(j1, j2);
        if (mwW != mwN) a -= 100.f;
        sc[n * 50 + m] = a;
    }
    __syncthreads();

    int wid = tid >> 5, lane = tid & 31;
    for (int n = wid; n < 49; n += 4) {
        float v1 = sc[n * 50 + lane];
        bool has2 = (lane + 32) < 49;
        float v2 = has2 ? sc[n * 50 + lane + 32] : -INFINITY;
        float mx = fmaxf(v1, v2);
        #pragma unroll
        for (int o = 16; o > 0; o >>= 1) mx = fmaxf(mx, __shfl_xor_sync(0xffffffffu, mx, o));
        float e1 = __expf(v1 - mx);
        float e2 = has2 ? __expf(v2 - mx) : 0.f;
        float s = e1 + e2;
        #pragma unroll
        for (int o = 16; o > 0; o >>= 1) s += __shfl_xor_sync(0xffffffffu, s, o);
        float inv = 1.f / s;
        sc[n * 50 + lane] = e1 * inv;
        if (has2) sc[n * 50 + lane + 32] = e2 * inv;
    }
    __syncthreads();

    for (int e = tid; e < 49 * 32; e += 128) {
        int n = e >> 5, d = e & 31;
        float a = 0.f;
        #pragma unroll
        for (int m = 0; m < 49; m++) a += sc[n * 50 + m] * vv[m * 33 + d];
        g_xw[((size_t)bw * NTOK + n) * CCH + h * 32 + d] = a;
    }
}

// ---------------- TF32 tensor-core GEMM:  C = A[M,K] @ W[N,K]^T + bias ----------------
// EPI 0: qkv (out g_big stride 384, q cols scaled)   EPI 1: proj (scatter + residual)
// EPI 2: fc1 (out g_big stride 512, exact GELU)      EPI 3: fc2 (A=g_big, out + g_x2)
// SMEM layout: operand pairs (k, k+4) packed as uint2; idx = r*136 + (m ^ 2r)
// where r = (k>>3)*4 + (k&3). Conflict-free LDS.64 fragment loads and STS.
template <int EPI>
__global__ void __launch_bounds__(256, 2)
mma_gemm(const float* __restrict__ W, const float* __restrict__ bias,
         const float* __restrict__ aux, float* __restrict__ extC,
         int M, int N, int K) {
    __shared__ uint2 As[8 * 136];
    __shared__ uint2 Bs[8 * 136];
    const float* A = (EPI == 3) ? g_big : g_xw;

    int tid = threadIdx.x, lane = tid & 31, warp = tid >> 5;
    int row0 = blockIdx.x * 128, col0 = blockIdx.y * 128;
    int wm = warp & 1, wn = warp >> 1;
    int g = lane >> 2, tg = lane & 3;

    int lm  = tid >> 1;      // row within tile 0..127
    int sel = tid & 1;       // k-half selector
    const float* Ap = A + (size_t)(row0 + lm) * K + sel * 8;
    const float* Wp = W + (size_t)(col0 + lm) * K + sel * 8;
    bool aok = (row0 + lm) < M;

    float acc[4][4][4];
    #pragma unroll
    for (int i = 0; i < 4; i++)
        #pragma unroll
        for (int j = 0; j < 4; j++)
            #pragma unroll
            for (int e = 0; e < 4; e++) acc[i][j][e] = 0.f;

    for (int kt = 0; kt < K; kt += 16) {
        float4 av0 = aok ? *(const float4*)(Ap + kt)     : make_float4(0,0,0,0);
        float4 av1 = aok ? *(const float4*)(Ap + kt + 4) : make_float4(0,0,0,0);
        float4 wv0 = *(const float4*)(Wp + kt);
        float4 wv1 = *(const float4*)(Wp + kt + 4);
        __syncthreads();
        {
            float a0[4] = {av0.x, av0.y, av0.z, av0.w};
            float a1[4] = {av1.x, av1.y, av1.z, av1.w};
            float w0[4] = {wv0.x, wv0.y, wv0.z, wv0.w};
            float w1[4] = {wv1.x, wv1.y, wv1.z, wv1.w};
            #pragma unroll
            for (int i = 0; i < 4; i++) {
                int r = sel * 4 + i;
                int idx = r * 136 + (lm ^ (2 * r));
                As[idx] = make_uint2(f2tf(a0[i]), f2tf(a1[i]));
                Bs[idx] = make_uint2(f2tf(w0[i]), f2tf(w1[i]));
            }
        }
        __syncthreads();
        #pragma unroll
        for (int ks = 0; ks < 2; ks++) {
            int rr = ks * 4 + tg;
            int srow = rr * 136, sw = 2 * rr;
            uint2 aF[4][2], bF[4];
            #pragma unroll
            for (int mf = 0; mf < 4; mf++) {
                int m0 = wm * 64 + mf * 16 + g;
                aF[mf][0] = As[srow + (m0 ^ sw)];
                aF[mf][1] = As[srow + ((m0 + 8) ^ sw)];
            }
            #pragma unroll
            for (int nf = 0; nf < 4; nf++)
                bF[nf] = Bs[srow + ((wn * 32 + nf * 8 + g) ^ sw)];
            #pragma unroll
            for (int mf = 0; mf < 4; mf++)
                #pragma unroll
                for (int nf = 0; nf < 4; nf++)
                    mma_tf32(acc[mf][nf], aF[mf][0].x, aF[mf][1].x,
                             aF[mf][0].y, aF[mf][1].y, bF[nf].x, bF[nf].y);
        }
    }

    // epilogue
    #pragma unroll
    for (int mf = 0; mf < 4; mf++) {
        #pragma unroll
        for (int h = 0; h < 2; h++) {
            int r = row0 + wm * 64 + mf * 16 + g + h * 8;
            if (r >= M) continue;
            size_t dest = 0;
            if (EPI == 1) {
                int bw = r / 49, tok = r - bw * 49;
                int bb = bw / 49, wi = bw - bb * 49;
                int R  = (wi / 7) * 7 + tok / 7;
                int Cl = (wi % 7) * 7 + tok % 7;
                int rr = R + 3;  if (rr >= 49) rr -= 49;
                int cc = Cl + 3; if (cc >= 49) cc -= 49;
                dest = ((size_t)bb * 2401 + rr * 49 + cc) * 128;
            }
            #pragma unroll
            for (int nf = 0; nf < 4; nf++) {
                #pragma unroll
                for (int e = 0; e < 2; e++) {
                    int n = col0 + wn * 32 + nf * 8 + tg * 2 + e;
                    float v = acc[mf][nf][h * 2 + e] + bias[n];
                    if (EPI == 0) {
                        if (n < 128) v *= QSCALE;
                        g_big[(size_t)r * 384 + n] = v;
                    } else if (EPI == 1) {
                        g_x2[dest + n] = aux[dest + n] + v;
                    } else if (EPI == 2) {
                        v = 0.5f * v * (1.f + erff(v * 0.70710678118654752f));
                        g_big[(size_t)r * 512 + n] = v;
                    } else {
                        extC[(size_t)r * 128 + n] = g_x2[(size_t)r * 128 + n] + v;
                    }
                }
            }
        }
    }
}

// ---------------- launch ----------------
extern "C" void kernel_launch(void* const* d_in, const int* in_sizes, int n_in,
                              void* d_out, int out_size) {
    const float* x      = (const float*)d_in[0];
    const float* n1w    = (const float*)d_in[1];
    const float* n1b    = (const float*)d_in[2];
    const float* qkv_w  = (const float*)d_in[3];
    const float* qkv_b  = (const float*)d_in[4];
    const float* proj_w = (const float*)d_in[5];
    const float* proj_b = (const float*)d_in[6];
    const float* rpb    = (const float*)d_in[7];
    const float* n2w    = (const float*)d_in[8];
    const float* n2b    = (const float*)d_in[9];
    const float* fc1_w  = (const float*)d_in[10];
    const float* fc1_b  = (const float*)d_in[11];
    const float* fc2_w  = (const float*)d_in[12];
    const float* fc2_b  = (const float*)d_in[13];
    float* out = (float*)d_out;

    const int M = MROWS;
    const int gm = (M + 127) / 128;   // 901

    ln1_gather_kernel<<<M, 128>>>(x, n1w, n1b);
    mma_gemm<0><<<dim3(gm, 3), 256>>>(qkv_w, qkv_b, nullptr, nullptr, M, 384, 128);
    attn_kernel<<<dim3(BN * NWIN, NHEAD), 128>>>(rpb);
    mma_gemm<1><<<dim3(gm, 1), 256>>>(proj_w, proj_b, x, nullptr, M, 128, 128);
    ln2_kernel<<<M, 128>>>(n2w, n2b);
    mma_gemm<2><<<dim3(gm, 4), 256>>>(fc1_w, fc1_b, nullptr, nullptr, M, 512, 128);
    mma_gemm<3><<<dim3(gm, 1), 256>>>(fc2_w, fc2_b, nullptr, out, M, 128, 512);
}

// round 3
// speedup vs baseline: 2.0701x; 1.2604x over previous
#include <cuda_runtime.h>
#include <cuda_bf16.h>
#include <math.h>
#include <stdint.h>

// ---------------- problem constants ----------------
#define BN    48
#define CCH   128
#define NWIN  49
#define NTOK  49
#define MROWS (BN*NWIN*NTOK)   // 115248
#define HID   512
#define QSCALE 0.17677669529663687f

// ---------------- scratch (device globals) ----------------
__device__ __nv_bfloat16 g_xw [(size_t)MROWS*CCH];   // LN1 out -> attn out -> LN2 out
__device__ __nv_bfloat16 g_big[(size_t)MROWS*HID];   // qkv (stride 384) then hidden (stride 512)
__device__ float         g_x2 [(size_t)MROWS*CCH];   // fp32 residual
__device__ __nv_bfloat16 g_wts[196608];              // qkv|proj|fc1|fc2 weights in bf16
#define WOFF_QKV 0
#define WOFF_PROJ 49152
#define WOFF_FC1  65536
#define WOFF_FC2  131072

// ---------------- asm helpers ----------------
__device__ __forceinline__ uint32_t smem_u32(const void* p) {
    return (uint32_t)__cvta_generic_to_shared(p);
}
__device__ __forceinline__ void cp_async16(uint32_t dst, const void* src, int sz) {
    asm volatile("cp.async.cg.shared.global [%0], [%1], 16, %2;"
                 :: "r"(dst), "l"(src), "r"(sz));
}
__device__ __forceinline__ void ldsm_x4(uint32_t r[4], uint32_t addr) {
    asm volatile("ldmatrix.sync.aligned.m8n8.x4.shared.b16 {%0,%1,%2,%3}, [%4];"
                 : "=r"(r[0]), "=r"(r[1]), "=r"(r[2]), "=r"(r[3]) : "r"(addr));
}
__device__ __forceinline__ void mma_bf16(float c[4], const uint32_t a[4],
                                         uint32_t b0, uint32_t b1) {
    asm volatile("mma.sync.aligned.m16n8k16.row.col.f32.bf16.bf16.f32 "
                 "{%0,%1,%2,%3}, {%4,%5,%6,%7}, {%8,%9}, {%0,%1,%2,%3};"
                 : "+f"(c[0]), "+f"(c[1]), "+f"(c[2]), "+f"(c[3])
                 : "r"(a[0]), "r"(a[1]), "r"(a[2]), "r"(a[3]), "r"(b0), "r"(b1));
}

// ---------------- weight convert (fp32 -> bf16, once per launch) ----------------
__global__ void cvt_weights(const float* __restrict__ qkv_w, const float* __restrict__ proj_w,
                            const float* __restrict__ fc1_w, const float* __restrict__ fc2_w) {
    int i = blockIdx.x * 256 + threadIdx.x;
    if (i < 49152)       g_wts[WOFF_QKV  + i] = __float2bfloat16_rn(qkv_w[i]);
    if (i < 16384)       g_wts[WOFF_PROJ + i] = __float2bfloat16_rn(proj_w[i]);
    if (i < 65536) {     g_wts[WOFF_FC1  + i] = __float2bfloat16_rn(fc1_w[i]);
                         g_wts[WOFF_FC2  + i] = __float2bfloat16_rn(fc2_w[i]); }
}

// ---------------- LN1 + shift + window gather (out bf16) ----------------
__global__ void ln1_gather_kernel(const float* __restrict__ x,
                                  const float* __restrict__ w,
                                  const float* __restrict__ b) {
    int t = blockIdx.x, c = threadIdx.x;
    int bw = t / NTOK, n = t - bw * NTOK;
    int bb = bw / NWIN, wi = bw - bb * NWIN;
    int R  = (wi / 7) * 7 + n / 7;
    int Cl = (wi % 7) * 7 + n % 7;
    int sr = R + 3;  if (sr >= 49) sr -= 49;
    int sc = Cl + 3; if (sc >= 49) sc -= 49;
    float v = x[((size_t)bb * 2401 + sr * 49 + sc) * CCH + c];
    float s = v, s2 = v * v;
    #pragma unroll
    for (int o = 16; o > 0; o >>= 1) {
        s  += __shfl_xor_sync(0xffffffffu, s,  o);
        s2 += __shfl_xor_sync(0xffffffffu, s2, o);
    }
    __shared__ float red[8];
    int wid = c >> 5, lane = c & 31;
    if (lane == 0) { red[wid] = s; red[4 + wid] = s2; }
    __syncthreads();
    float ts  = red[0] + red[1] + red[2] + red[3];
    float ts2 = red[4] + red[5] + red[6] + red[7];
    float mean = ts * (1.f / 128.f);
    float var  = ts2 * (1.f / 128.f) - mean * mean;
    float rstd = rsqrtf(var + 1e-5f);
    g_xw[(size_t)t * CCH + c] = __float2bfloat16_rn((v - mean) * rstd * w[c] + b[c]);
}

__global__ void ln2_kernel(const float* __restrict__ w,
                           const float* __restrict__ b) {
    int t = blockIdx.x, c = threadIdx.x;
    float v = g_x2[(size_t)t * CCH + c];
    float s = v, s2 = v * v;
    #pragma unroll
    for (int o = 16; o > 0; o >>= 1) {
        s  += __shfl_xor_sync(0xffffffffu, s,  o);
        s2 += __shfl_xor_sync(0xffffffffu, s2, o);
    }
    __shared__ float red[8];
    int wid = c >> 5, lane = c & 31;
    if (lane == 0) { red[wid] = s; red[4 + wid] = s2; }
    __syncthreads();
    float ts  = red[0] + red[1] + red[2] + red[3];
    float ts2 = red[4] + red[5] + red[6] + red[7];
    float mean = ts * (1.f / 128.f);
    float var  = ts2 * (1.f / 128.f) - mean * mean;
    float rstd = rsqrtf(var + 1e-5f);
    g_xw[(size_t)t * CCH + c] = __float2bfloat16_rn((v - mean) * rstd * w[c] + b[c]);
}

// ---------------- attention ----------------
__device__ __forceinline__ int regn(int wq, int iq) {
    return (wq < 6) ? 0 : ((iq < 4) ? 1 : 2);
}

__global__ void attn_kernel(const float* __restrict__ rpb) {
    int bw = blockIdx.x, h = blockIdx.y;
    int w  = bw % NWIN;
    int tid = threadIdx.x;

    __shared__ float q [49 * 33];
    __shared__ float k [49 * 33];
    __shared__ float vv[49 * 33];
    __shared__ float sc[49 * 50];

    const __nv_bfloat16* base = g_big + (size_t)bw * NTOK * 384;
    for (int idx = tid; idx < 49 * 32; idx += 128) {
        int n = idx >> 5, d = idx & 31;
        q [n * 33 + d] = __bfloat162float(base[n * 384 +       h * 32 + d]);
        k [n * 33 + d] = __bfloat162float(base[n * 384 + 128 + h * 32 + d]);
        vv[n * 33 + d] = __bfloat162float(base[n * 384 + 256 + h * 32 + d]);
    }
    __syncthreads();

    int wh = w / 7, ww = w % 7;
    for (int e = tid; e < 49 * 49; e += 128) {
        int n = e / 49, m = e - n * 49;
        float a = 0.f;
        #pragma unroll
        for (int d = 0; d < 32; d++) a += q[n * 33 + d] * k[m * 33 + d];
        int i1 = n / 7, j1 = n % 7, i2 = m / 7, j2 = m % 7;
        int ridx = (i1 - i2 + 6) * 13 + (j1 - j2 + 6);
        a += rpb[ridx * 4 + h];
        int mwW = regn(wh, i2) * 3 + regn(ww, j2);
        int mwN = regn(i1, i2) * 3 + regn(j1, j2);
        if (mwW != mwN) a -= 100.f;
        sc[n * 50 + m] = a;
    }
    __syncthreads();

    int wid = tid >> 5, lane = tid & 31;
    for (int n = wid; n < 49; n += 4) {
        float v1 = sc[n * 50 + lane];
        bool has2 = (lane + 32) < 49;
        float v2 = has2 ? sc[n * 50 + lane + 32] : -INFINITY;
        float mx = fmaxf(v1, v2);
        #pragma unroll
        for (int o = 16; o > 0; o >>= 1) mx = fmaxf(mx, __shfl_xor_sync(0xffffffffu, mx, o));
        float e1 = __expf(v1 - mx);
        float e2 = has2 ? __expf(v2 - mx) : 0.f;
        float s = e1 + e2;
        #pragma unroll
        for (int o = 16; o > 0; o >>= 1) s += __shfl_xor_sync(0xffffffffu, s, o);
        float inv = 1.f / s;
        sc[n * 50 + lane] = e1 * inv;
        if (has2) sc[n * 50 + lane + 32] = e2 * inv;
    }
    __syncthreads();

    for (int e = tid; e < 49 * 32; e += 128) {
        int n = e >> 5, d = e & 31;
        float a = 0.f;
        #pragma unroll
        for (int m = 0; m < 49; m++) a += sc[n * 50 + m] * vv[m * 33 + d];
        g_xw[((size_t)bw * NTOK + n) * CCH + h * 32 + d] = __float2bfloat16_rn(a);
    }
}

// ---------------- bf16 tensor-core GEMM with cp.async pipeline ----------------
// C = A[M,K](bf16) @ W[N,K](bf16)^T + bias, fused epilogues (same EPI meanings).
// SMEM tile: 128 rows x 32 k (bf16) per operand per stage; 16B chunk swizzle:
//   off(r,c) = r*64 + (c ^ ((r>>1)&3))*16        (c = 0..3)
// Conflict-free for cp.async stores and ldmatrix reads.
#define BK 32
#define STAGES 3
#define TILE_B 8192          // one operand, one stage

template <int EPI>
__global__ void __launch_bounds__(256, 2)
mma_gemm(const __nv_bfloat16* __restrict__ Wb, const float* __restrict__ bias,
         const float* __restrict__ aux, float* __restrict__ extC,
         int M, int N, int K) {
    __shared__ __align__(16) uint8_t smem[STAGES * 2 * TILE_B];

    const __nv_bfloat16* A = (EPI == 3) ? g_big : g_xw;
    const int lda = (EPI == 3) ? 512 : 128;

    int tid = threadIdx.x, lane = tid & 31, warp = tid >> 5;
    int row0 = blockIdx.x * 128, col0 = blockIdx.y * 128;
    int wm = warp & 1, wn = warp >> 1;
    int g = lane >> 2, tg = lane & 3;

    float acc[4][4][4];
    #pragma unroll
    for (int i = 0; i < 4; i++)
        #pragma unroll
        for (int j = 0; j < 4; j++)
            #pragma unroll
            for (int e = 0; e < 4; e++) acc[i][j][e] = 0.f;

    uint32_t sbase = smem_u32(smem);
    const int nkt = K / BK;

    // -------- tile loader --------
    auto load_tile = [&](int kt, int st) {
        uint32_t sa = sbase + st * 2 * TILE_B;
        uint32_t sb = sa + TILE_B;
        #pragma unroll
        for (int h = 0; h < 2; h++) {
            int id = tid + h * 256;
            int r = id >> 2, c = id & 3;
            uint32_t off = r * 64 + ((c ^ ((r >> 1) & 3)) << 4);
            const __nv_bfloat16* ga = A + (size_t)(row0 + r) * lda + kt * BK + c * 8;
            cp_async16(sa + off, ga, (row0 + r) < M ? 16 : 0);
            const __nv_bfloat16* gb = Wb + (size_t)(col0 + r) * K + kt * BK + c * 8;
            cp_async16(sb + off, gb, 16);
        }
        asm volatile("cp.async.commit_group;");
    };

    // -------- prologue --------
    load_tile(0, 0);
    load_tile(1, 1);

    // -------- mainloop --------
    for (int kt = 0; kt < nkt; kt++) {
        if (kt < nkt - 1) asm volatile("cp.async.wait_group 1;");
        else              asm volatile("cp.async.wait_group 0;");
        __syncthreads();
        if (kt + 2 < nkt) load_tile(kt + 2, (kt + 2) % STAGES);

        int st = kt % STAGES;
        uint32_t sa = sbase + st * 2 * TILE_B;
        uint32_t sb = sa + TILE_B;
        #pragma unroll
        for (int ks = 0; ks < 2; ks++) {
            uint32_t aF[4][4], bF[2][4];
            #pragma unroll
            for (int mf = 0; mf < 4; mf++) {
                int r = wm * 64 + mf * 16 + (lane & 15);
                int c = 2 * ks + (lane >> 4);
                ldsm_x4(aF[mf], sa + r * 64 + ((c ^ ((r >> 1) & 3)) << 4));
            }
            #pragma unroll
            for (int nfp = 0; nfp < 2; nfp++) {
                int r = wn * 32 + nfp * 16 + (lane & 7) + ((lane >> 4) & 1) * 8;
                int c = 2 * ks + ((lane >> 3) & 1);
                ldsm_x4(bF[nfp], sb + r * 64 + ((c ^ ((r >> 1) & 3)) << 4));
            }
            #pragma unroll
            for (int mf = 0; mf < 4; mf++)
                #pragma unroll
                for (int nf = 0; nf < 4; nf++)
                    mma_bf16(acc[mf][nf], aF[mf],
                             bF[nf >> 1][(nf & 1) * 2], bF[nf >> 1][(nf & 1) * 2 + 1]);
        }
    }

    // -------- epilogue --------
    #pragma unroll
    for (int mf = 0; mf < 4; mf++) {
        #pragma unroll
        for (int h = 0; h < 2; h++) {
            int r = row0 + wm * 64 + mf * 16 + g + h * 8;
            if (r >= M) continue;
            size_t dest = 0;
            if (EPI == 1) {
                int bw = r / 49, tok = r - bw * 49;
                int bb = bw / 49, wi = bw - bb * 49;
                int R  = (wi / 7) * 7 + tok / 7;
                int Cl = (wi % 7) * 7 + tok % 7;
                int rr = R + 3;  if (rr >= 49) rr -= 49;
                int cc = Cl + 3; if (cc >= 49) cc -= 49;
                dest = ((size_t)bb * 2401 + rr * 49 + cc) * 128;
            }
            #pragma unroll
            for (int nf = 0; nf < 4; nf++) {
                #pragma unroll
                for (int e = 0; e < 2; e++) {
                    int n = col0 + wn * 32 + nf * 8 + tg * 2 + e;
                    float v = acc[mf][nf][h * 2 + e] + bias[n];
                    if (EPI == 0) {
                        if (n < 128) v *= QSCALE;
                        g_big[(size_t)r * 384 + n] = __float2bfloat16_rn(v);
                    } else if (EPI == 1) {
                        g_x2[dest + n] = aux[dest + n] + v;
                    } else if (EPI == 2) {
                        v = 0.5f * v * (1.f + erff(v * 0.70710678118654752f));
                        g_big[(size_t)r * 512 + n] = __float2bfloat16_rn(v);
                    } else {
                        extC[(size_t)r * 128 + n] = g_x2[(size_t)r * 128 + n] + v;
                    }
                }
            }
        }
    }
}

// ---------------- launch ----------------
extern "C" void kernel_launch(void* const* d_in, const int* in_sizes, int n_in,
                              void* d_out, int out_size) {
    const float* x      = (const float*)d_in[0];
    const float* n1w    = (const float*)d_in[1];
    const float* n1b    = (const float*)d_in[2];
    const float* qkv_w  = (const float*)d_in[3];
    const float* qkv_b  = (const float*)d_in[4];
    const float* proj_w = (const float*)d_in[5];
    const float* proj_b = (const float*)d_in[6];
    const float* rpb    = (const float*)d_in[7];
    const float* n2w    = (const float*)d_in[8];
    const float* n2b    = (const float*)d_in[9];
    const float* fc1_w  = (const float*)d_in[10];
    const float* fc1_b  = (const float*)d_in[11];
    const float* fc2_w  = (const float*)d_in[12];
    const float* fc2_b  = (const float*)d_in[13];
    float* out = (float*)d_out;

    const int M = MROWS;
    const int gm = (M + 127) / 128;   // 901

    __nv_bfloat16* wq = nullptr;  // offsets into g_wts resolved device-side

    cvt_weights<<<256, 256>>>(qkv_w, proj_w, fc1_w, fc2_w);
    ln1_gather_kernel<<<M, 128>>>(x, n1w, n1b);

    // device pointers to g_wts segments
    __nv_bfloat16* wbase;
    cudaGetSymbolAddress((void**)&wbase, g_wts);

    mma_gemm<0><<<dim3(gm, 3), 256>>>(wbase + WOFF_QKV, qkv_b, nullptr, nullptr, M, 384, 128);
    attn_kernel<<<dim3(BN * NWIN, 4), 128>>>(rpb);
    mma_gemm<1><<<dim3(gm, 1), 256>>>(wbase + WOFF_PROJ, proj_b, x, nullptr, M, 128, 128);
    ln2_kernel<<<M, 128>>>(n2w, n2b);
    mma_gemm<2><<<dim3(gm, 4), 256>>>(wbase + WOFF_FC1, fc1_b, nullptr, nullptr, M, 512, 128);
    mma_gemm<3><<<dim3(gm, 1), 256>>>(wbase + WOFF_FC2, fc2_b, nullptr, out, M, 128, 512);
    (void)wq;
}

// round 4
// speedup vs baseline: 3.0298x; 1.4636x over previous
#include <cuda_runtime.h>
#include <cuda_bf16.h>
#include <math.h>
#include <stdint.h>

// ---------------- problem constants ----------------
#define BN    48
#define CCH   128
#define NWIN  49
#define NTOK  49
#define MROWS (BN*NWIN*NTOK)   // 115248
#define HID   512
#define QSCALE 0.17677669529663687f

// ---------------- scratch (device globals) ----------------
__device__ __nv_bfloat16 g_xw [(size_t)MROWS*CCH];
__device__ __nv_bfloat16 g_big[(size_t)MROWS*HID];
__device__ float         g_x2 [(size_t)MROWS*CCH];
__device__ __nv_bfloat16 g_wts[196608];
__device__ float         g_bm [49*4*64*64];          // bias+mask table
#define WOFF_QKV 0
#define WOFF_PROJ 49152
#define WOFF_FC1  65536
#define WOFF_FC2  131072

// ---------------- asm helpers ----------------
__device__ __forceinline__ uint32_t smem_u32(const void* p) {
    return (uint32_t)__cvta_generic_to_shared(p);
}
__device__ __forceinline__ void cp_async16(uint32_t dst, const void* src, int sz) {
    asm volatile("cp.async.cg.shared.global [%0], [%1], 16, %2;"
                 :: "r"(dst), "l"(src), "r"(sz));
}
__device__ __forceinline__ void ldsm_x4(uint32_t r[4], uint32_t addr) {
    asm volatile("ldmatrix.sync.aligned.m8n8.x4.shared.b16 {%0,%1,%2,%3}, [%4];"
                 : "=r"(r[0]), "=r"(r[1]), "=r"(r[2]), "=r"(r[3]) : "r"(addr));
}
__device__ __forceinline__ void ldsm_x4_t(uint32_t r[4], uint32_t addr) {
    asm volatile("ldmatrix.sync.aligned.m8n8.x4.trans.shared.b16 {%0,%1,%2,%3}, [%4];"
                 : "=r"(r[0]), "=r"(r[1]), "=r"(r[2]), "=r"(r[3]) : "r"(addr));
}
__device__ __forceinline__ void mma_bf16(float c[4], const uint32_t a[4],
                                         uint32_t b0, uint32_t b1) {
    asm volatile("mma.sync.aligned.m16n8k16.row.col.f32.bf16.bf16.f32 "
                 "{%0,%1,%2,%3}, {%4,%5,%6,%7}, {%8,%9}, {%0,%1,%2,%3};"
                 : "+f"(c[0]), "+f"(c[1]), "+f"(c[2]), "+f"(c[3])
                 : "r"(a[0]), "r"(a[1]), "r"(a[2]), "r"(a[3]), "r"(b0), "r"(b1));
}

// ---------------- weight convert ----------------
__global__ void cvt_weights(const float* __restrict__ qkv_w, const float* __restrict__ proj_w,
                            const float* __restrict__ fc1_w, const float* __restrict__ fc2_w) {
    int i = blockIdx.x * 256 + threadIdx.x;
    if (i < 49152)       g_wts[WOFF_QKV  + i] = __float2bfloat16_rn(qkv_w[i]);
    if (i < 16384)       g_wts[WOFF_PROJ + i] = __float2bfloat16_rn(proj_w[i]);
    if (i < 65536) {     g_wts[WOFF_FC1  + i] = __float2bfloat16_rn(fc1_w[i]);
                         g_wts[WOFF_FC2  + i] = __float2bfloat16_rn(fc2_w[i]); }
}

// ---------------- bias+mask table ----------------
__device__ __forceinline__ int regn(int wq, int iq) {
    return (wq < 6) ? 0 : ((iq < 4) ? 1 : 2);
}
__global__ void build_bm(const float* __restrict__ rpb) {
    int w = blockIdx.x, h = blockIdx.y;
    int wh = w / 7, ww = w % 7;
    for (int e = threadIdx.x; e < 64 * 64; e += 256) {
        int n = e >> 6, m = e & 63;
        float v;
        if (n < 49 && m < 49) {
            int i1 = n / 7, j1 = n % 7, i2 = m / 7, j2 = m % 7;
            v = rpb[((i1 - i2 + 6) * 13 + (j1 - j2 + 6)) * 4 + h];
            int mwW = regn(wh, i2) * 3 + regn(ww, j2);
            int mwN = regn(i1, i2) * 3 + regn(j1, j2);
            if (mwW != mwN) v -= 100.f;
        } else {
            v = -1e9f;
        }
        g_bm[((size_t)(w * 4 + h) * 64 + n) * 64 + m] = v;
    }
}

// ---------------- LN1 + shift + window gather ----------------
__global__ void ln1_gather_kernel(const float* __restrict__ x,
                                  const float* __restrict__ w,
                                  const float* __restrict__ b) {
    int t = blockIdx.x, c = threadIdx.x;
    int bw = t / NTOK, n = t - bw * NTOK;
    int bb = bw / NWIN, wi = bw - bb * NWIN;
    int R  = (wi / 7) * 7 + n / 7;
    int Cl = (wi % 7) * 7 + n % 7;
    int sr = R + 3;  if (sr >= 49) sr -= 49;
    int sc = Cl + 3; if (sc >= 49) sc -= 49;
    float v = x[((size_t)bb * 2401 + sr * 49 + sc) * CCH + c];
    float s = v, s2 = v * v;
    #pragma unroll
    for (int o = 16; o > 0; o >>= 1) {
        s  += __shfl_xor_sync(0xffffffffu, s,  o);
        s2 += __shfl_xor_sync(0xffffffffu, s2, o);
    }
    __shared__ float red[8];
    int wid = c >> 5, lane = c & 31;
    if (lane == 0) { red[wid] = s; red[4 + wid] = s2; }
    __syncthreads();
    float ts  = red[0] + red[1] + red[2] + red[3];
    float ts2 = red[4] + red[5] + red[6] + red[7];
    float mean = ts * (1.f / 128.f);
    float var  = ts2 * (1.f / 128.f) - mean * mean;
    float rstd = rsqrtf(var + 1e-5f);
    g_xw[(size_t)t * CCH + c] = __float2bfloat16_rn((v - mean) * rstd * w[c] + b[c]);
}

__global__ void ln2_kernel(const float* __restrict__ w,
                           const float* __restrict__ b) {
    int t = blockIdx.x, c = threadIdx.x;
    float v = g_x2[(size_t)t * CCH + c];
    float s = v, s2 = v * v;
    #pragma unroll
    for (int o = 16; o > 0; o >>= 1) {
        s  += __shfl_xor_sync(0xffffffffu, s,  o);
        s2 += __shfl_xor_sync(0xffffffffu, s2, o);
    }
    __shared__ float red[8];
    int wid = c >> 5, lane = c & 31;
    if (lane == 0) { red[wid] = s; red[4 + wid] = s2; }
    __syncthreads();
    float ts  = red[0] + red[1] + red[2] + red[3];
    float ts2 = red[4] + red[5] + red[6] + red[7];
    float mean = ts * (1.f / 128.f);
    float var  = ts2 * (1.f / 128.f) - mean * mean;
    float rstd = rsqrtf(var + 1e-5f);
    g_xw[(size_t)t * CCH + c] = __float2bfloat16_rn((v - mean) * rstd * w[c] + b[c]);
}

// ---------------- tensor-core attention: one block per (window, head) ----------------
// Padded 64x64 problem. S = Q@K^T via bf16 MMA, register softmax (quad shuffles),
// P -> smem bf16 (swizzled), P@V via ldmatrix(.trans for V).
__global__ void __launch_bounds__(128) attn_kernel() {
    int bw = blockIdx.x, h = blockIdx.y;
    int w  = bw % NWIN;
    int tid = threadIdx.x, lane = tid & 31, warp = tid >> 5;

    __shared__ __align__(16) uint8_t sQ[64 * 64];
    __shared__ __align__(16) uint8_t sK[64 * 64];
    __shared__ __align__(16) uint8_t sV[64 * 64];
    __shared__ __align__(16) uint8_t sP[64 * 128];

    uint32_t qb = smem_u32(sQ), kb = smem_u32(sK);
    uint32_t vb = smem_u32(sV), pb = smem_u32(sP);

    const __nv_bfloat16* base = g_big + (size_t)bw * NTOK * 384;
    // load Q,K,V: 3 ops x 64 rows x 4 chunks (16B); rows >= 49 zero-filled
    for (int id = tid; id < 768; id += 128) {
        int op = id >> 8;
        int r  = (id >> 2) & 63;
        int c  = id & 3;
        uint32_t sb = (op == 0) ? qb : (op == 1) ? kb : vb;
        uint32_t dst = sb + r * 64 + ((c ^ ((r >> 1) & 3)) << 4);
        const __nv_bfloat16* src = base + (r < 49 ? r : 0) * 384 + op * 128 + h * 32 + c * 8;
        cp_async16(dst, src, r < 49 ? 16 : 0);
    }
    asm volatile("cp.async.commit_group;");
    asm volatile("cp.async.wait_group 0;");
    __syncthreads();

    int g = lane >> 2, tg = lane & 3;
    int m0 = warp * 16;

    // ---- S = Q @ K^T  (per-warp m16 x n64, k32) ----
    float acc[8][4];
    #pragma unroll
    for (int i = 0; i < 8; i++)
        #pragma unroll
        for (int j = 0; j < 4; j++) acc[i][j] = 0.f;

    #pragma unroll
    for (int ks = 0; ks < 2; ks++) {
        uint32_t aF[4];
        {
            int r = m0 + (lane & 15);
            int c = 2 * ks + (lane >> 4);
            ldsm_x4(aF, qb + r * 64 + ((c ^ ((r >> 1) & 3)) << 4));
        }
        #pragma unroll
        for (int nfp = 0; nfp < 4; nfp++) {
            uint32_t bF[4];
            int r = nfp * 16 + (lane & 7) + ((lane >> 4) & 1) * 8;
            int c = 2 * ks + ((lane >> 3) & 1);
            ldsm_x4(bF, kb + r * 64 + ((c ^ ((r >> 1) & 3)) << 4));
            mma_bf16(acc[nfp * 2],     aF, bF[0], bF[1]);
            mma_bf16(acc[nfp * 2 + 1], aF, bF[2], bF[3]);
        }
    }

    // ---- bias+mask + softmax in registers, store P(bf16) to smem ----
    const float* bm = g_bm + (size_t)(w * 4 + h) * 64 * 64;
    #pragma unroll
    for (int hh = 0; hh < 2; hh++) {
        int n = m0 + g + hh * 8;
        const float* bmr = bm + n * 64;
        float vals[16];
        #pragma unroll
        for (int nf = 0; nf < 8; nf++) {
            float2 bv = *(const float2*)(bmr + nf * 8 + tg * 2);
            vals[nf * 2]     = acc[nf][hh * 2]     + bv.x;
            vals[nf * 2 + 1] = acc[nf][hh * 2 + 1] + bv.y;
        }
        float mx = vals[0];
        #pragma unroll
        for (int i = 1; i < 16; i++) mx = fmaxf(mx, vals[i]);
        mx = fmaxf(mx, __shfl_xor_sync(0xffffffffu, mx, 1));
        mx = fmaxf(mx, __shfl_xor_sync(0xffffffffu, mx, 2));
        float sum = 0.f;
        #pragma unroll
        for (int i = 0; i < 16; i++) { vals[i] = __expf(vals[i] - mx); sum += vals[i]; }
        sum += __shfl_xor_sync(0xffffffffu, sum, 1);
        sum += __shfl_xor_sync(0xffffffffu, sum, 2);
        float inv = 1.f / sum;
        #pragma unroll
        for (int nf = 0; nf < 8; nf++) {
            __nv_bfloat162 p;
            p.x = __float2bfloat16_rn(vals[nf * 2] * inv);
            p.y = __float2bfloat16_rn(vals[nf * 2 + 1] * inv);
            *(uint32_t*)(sP + n * 128 + ((nf ^ (n & 7)) << 4) + tg * 4) = *(uint32_t*)&p;
        }
    }
    __syncwarp();

    // ---- O = P @ V  (m16 x n32, k64) ----
    float acc2[4][4];
    #pragma unroll
    for (int i = 0; i < 4; i++)
        #pragma unroll
        for (int j = 0; j < 4; j++) acc2[i][j] = 0.f;

    #pragma unroll
    for (int ks = 0; ks < 4; ks++) {
        uint32_t aF[4];
        {
            int r = m0 + (lane & 15);
            int c = 2 * ks + (lane >> 4);
            ldsm_x4(aF, pb + r * 128 + ((c ^ (r & 7)) << 4));
        }
        #pragma unroll
        for (int nfp = 0; nfp < 2; nfp++) {
            uint32_t bF[4];
            int rv = ks * 16 + (lane & 7) + ((lane >> 3) & 1) * 8;
            int cv = nfp * 2 + (lane >> 4);
            ldsm_x4_t(bF, vb + rv * 64 + ((cv ^ ((rv >> 1) & 3)) << 4));
            mma_bf16(acc2[nfp * 2],     aF, bF[0], bF[1]);
            mma_bf16(acc2[nfp * 2 + 1], aF, bF[2], bF[3]);
        }
    }

    // ---- write attn out (bf16) ----
    #pragma unroll
    for (int hh = 0; hh < 2; hh++) {
        int n = m0 + g + hh * 8;
        if (n < 49) {
            __nv_bfloat16* dst = g_xw + ((size_t)bw * NTOK + n) * CCH + h * 32;
            #pragma unroll
            for (int nf = 0; nf < 4; nf++) {
                __nv_bfloat162 o;
                o.x = __float2bfloat16_rn(acc2[nf][hh * 2]);
                o.y = __float2bfloat16_rn(acc2[nf][hh * 2 + 1]);
                *(uint32_t*)(dst + nf * 8 + tg * 2) = *(uint32_t*)&o;
            }
        }
    }
}

// ---------------- bf16 tensor-core GEMM with cp.async pipeline ----------------
#define BK 32
#define STAGES 3
#define TILE_B 8192

template <int EPI>
__global__ void __launch_bounds__(256, 2)
mma_gemm(const __nv_bfloat16* __restrict__ Wb, const float* __restrict__ bias,
         const float* __restrict__ aux, float* __restrict__ extC,
         int M, int N, int K) {
    __shared__ __align__(16) uint8_t smem[STAGES * 2 * TILE_B];

    const __nv_bfloat16* A = (EPI == 3) ? g_big : g_xw;
    const int lda = (EPI == 3) ? 512 : 128;

    int tid = threadIdx.x, lane = tid & 31, warp = tid >> 5;
    int row0 = blockIdx.x * 128, col0 = blockIdx.y * 128;
    int wm = warp & 1, wn = warp >> 1;
    int g = lane >> 2, tg = lane & 3;

    float acc[4][4][4];
    #pragma unroll
    for (int i = 0; i < 4; i++)
        #pragma unroll
        for (int j = 0; j < 4; j++)
            #pragma unroll
            for (int e = 0; e < 4; e++) acc[i][j][e] = 0.f;

    uint32_t sbase = smem_u32(smem);
    const int nkt = K / BK;

    auto load_tile = [&](int kt, int st) {
        uint32_t sa = sbase + st * 2 * TILE_B;
        uint32_t sb = sa + TILE_B;
        #pragma unroll
        for (int h = 0; h < 2; h++) {
            int id = tid + h * 256;
            int r = id >> 2, c = id & 3;
            uint32_t off = r * 64 + ((c ^ ((r >> 1) & 3)) << 4);
            const __nv_bfloat16* ga = A + (size_t)(row0 + r) * lda + kt * BK + c * 8;
            cp_async16(sa + off, ga, (row0 + r) < M ? 16 : 0);
            const __nv_bfloat16* gb = Wb + (size_t)(col0 + r) * K + kt * BK + c * 8;
            cp_async16(sb + off, gb, 16);
        }
        asm volatile("cp.async.commit_group;");
    };

    load_tile(0, 0);
    load_tile(1, 1);

    for (int kt = 0; kt < nkt; kt++) {
        if (kt < nkt - 1) asm volatile("cp.async.wait_group 1;");
        else              asm volatile("cp.async.wait_group 0;");
        __syncthreads();
        if (kt + 2 < nkt) load_tile(kt + 2, (kt + 2) % STAGES);

        int st = kt % STAGES;
        uint32_t sa = sbase + st * 2 * TILE_B;
        uint32_t sb = sa + TILE_B;
        #pragma unroll
        for (int ks = 0; ks < 2; ks++) {
            uint32_t aF[4][4], bF[2][4];
            #pragma unroll
            for (int mf = 0; mf < 4; mf++) {
                int r = wm * 64 + mf * 16 + (lane & 15);
                int c = 2 * ks + (lane >> 4);
                ldsm_x4(aF[mf], sa + r * 64 + ((c ^ ((r >> 1) & 3)) << 4));
            }
            #pragma unroll
            for (int nfp = 0; nfp < 2; nfp++) {
                int r = wn * 32 + nfp * 16 + (lane & 7) + ((lane >> 4) & 1) * 8;
                int c = 2 * ks + ((lane >> 3) & 1);
                ldsm_x4(bF[nfp], sb + r * 64 + ((c ^ ((r >> 1) & 3)) << 4));
            }
            #pragma unroll
            for (int mf = 0; mf < 4; mf++)
                #pragma unroll
                for (int nf = 0; nf < 4; nf++)
                    mma_bf16(acc[mf][nf], aF[mf],
                             bF[nf >> 1][(nf & 1) * 2], bF[nf >> 1][(nf & 1) * 2 + 1]);
        }
    }

    #pragma unroll
    for (int mf = 0; mf < 4; mf++) {
        #pragma unroll
        for (int h = 0; h < 2; h++) {
            int r = row0 + wm * 64 + mf * 16 + g + h * 8;
            if (r >= M) continue;
            size_t dest = 0;
            if (EPI == 1) {
                int bw = r / 49, tok = r - bw * 49;
                int bb = bw / 49, wi = bw - bb * 49;
                int R  = (wi / 7) * 7 + tok / 7;
                int Cl = (wi % 7) * 7 + tok % 7;
                int rr = R + 3;  if (rr >= 49) rr -= 49;
                int cc = Cl + 3; if (cc >= 49) cc -= 49;
                dest = ((size_t)bb * 2401 + rr * 49 + cc) * 128;
            }
            #pragma unroll
            for (int nf = 0; nf < 4; nf++) {
                #pragma unroll
                for (int e = 0; e < 2; e++) {
                    int n = col0 + wn * 32 + nf * 8 + tg * 2 + e;
                    float v = acc[mf][nf][h * 2 + e] + bias[n];
                    if (EPI == 0) {
                        if (n < 128) v *= QSCALE;
                        g_big[(size_t)r * 384 + n] = __float2bfloat16_rn(v);
                    } else if (EPI == 1) {
                        g_x2[dest + n] = aux[dest + n] + v;
                    } else if (EPI == 2) {
                        v = 0.5f * v * (1.f + erff(v * 0.70710678118654752f));
                        g_big[(size_t)r * 512 + n] = __float2bfloat16_rn(v);
                    } else {
                        extC[(size_t)r * 128 + n] = g_x2[(size_t)r * 128 + n] + v;
                    }
                }
            }
        }
    }
}

// ---------------- launch ----------------
extern "C" void kernel_launch(void* const* d_in, const int* in_sizes, int n_in,
                              void* d_out, int out_size) {
    const float* x      = (const float*)d_in[0];
    const float* n1w    = (const float*)d_in[1];
    const float* n1b    = (const float*)d_in[2];
    const float* qkv_w  = (const float*)d_in[3];
    const float* qkv_b  = (const float*)d_in[4];
    const float* proj_w = (const float*)d_in[5];
    const float* proj_b = (const float*)d_in[6];
    const float* rpb    = (const float*)d_in[7];
    const float* n2w    = (const float*)d_in[8];
    const float* n2b    = (const float*)d_in[9];
    const float* fc1_w  = (const float*)d_in[10];
    const float* fc1_b  = (const float*)d_in[11];
    const float* fc2_w  = (const float*)d_in[12];
    const float* fc2_b  = (const float*)d_in[13];
    float* out = (float*)d_out;

    const int M = MROWS;
    const int gm = (M + 127) / 128;   // 901

    cvt_weights<<<256, 256>>>(qkv_w, proj_w, fc1_w, fc2_w);
    build_bm<<<dim3(49, 4), 256>>>(rpb);
    ln1_gather_kernel<<<M, 128>>>(x, n1w, n1b);

    __nv_bfloat16* wbase;
    cudaGetSymbolAddress((void**)&wbase, g_wts);

    mma_gemm<0><<<dim3(gm, 3), 256>>>(wbase + WOFF_QKV, qkv_b, nullptr, nullptr, M, 384, 128);
    attn_kernel<<<dim3(BN * NWIN, 4), 128>>>();
    mma_gemm<1><<<dim3(gm, 1), 256>>>(wbase + WOFF_PROJ, proj_b, x, nullptr, M, 128, 128);
    ln2_kernel<<<M, 128>>>(n2w, n2b);
    mma_gemm<2><<<dim3(gm, 4), 256>>>(wbase + WOFF_FC1, fc1_b, nullptr, nullptr, M, 512, 128);
    mma_gemm<3><<<dim3(gm, 1), 256>>>(wbase + WOFF_FC2, fc2_b, nullptr, out, M, 128, 512);
}